// round 3
// baseline (speedup 1.0000x reference)
#include <cuda_runtime.h>
#include <math_constants.h>

#define DHEAD   128
#define BQ      64
#define BK      64
#define THREADS 256

// ---------------- packed f32x2 helpers (sm_103a) ----------------
__device__ __forceinline__ unsigned long long pack2(float lo, float hi) {
    unsigned long long r;
    asm("mov.b64 %0, {%1, %2};" : "=l"(r) : "f"(lo), "f"(hi));
    return r;
}
__device__ __forceinline__ void unpack2(unsigned long long v, float& lo, float& hi) {
    asm("mov.b64 {%0, %1}, %2;" : "=f"(lo), "=f"(hi) : "l"(v));
}
__device__ __forceinline__ void ffma2(unsigned long long& acc,
                                      unsigned long long a, unsigned long long b) {
    asm("fma.rn.f32x2 %0, %1, %2, %0;" : "+l"(acc) : "l"(a), "l"(b));
}
__device__ __forceinline__ unsigned long long mul2(unsigned long long a, unsigned long long b) {
    unsigned long long r;
    asm("mul.rn.f32x2 %0, %1, %2;" : "=l"(r) : "l"(a), "l"(b));
    return r;
}

// Smem layout (floats):
//   Qs  [128][64]          8192
//   Ks  [128][64]          8192
//   Vts [64][132]          8448   (V transposed: row k, col d; stride 132 = 16B-aligned rows)
//   Ps  [64][68]           4352   (P transposed: row k, col q; stride 68 = 16B-aligned rows)
#define SM_QS   0
#define SM_KS   (128 * 64)
#define SM_VTS  (SM_KS + 128 * 64)
#define SM_PS   (SM_VTS + 64 * 132)
#define SM_FLOATS (SM_PS + 64 * 68)
#define SM_BYTES  (SM_FLOATS * 4)

__global__ void __launch_bounds__(THREADS, 1)
attn_flash_f32x2_kernel(const float* __restrict__ Q,
                        const float* __restrict__ K,
                        const float* __restrict__ V,
                        float* __restrict__ Out,
                        int n)
{
    extern __shared__ float sm[];
    float* Qs  = sm + SM_QS;
    float* Ks  = sm + SM_KS;
    float* Vts = sm + SM_VTS;
    float* Ps  = sm + SM_PS;

    const int tid = threadIdx.x;
    const int tq  = tid >> 4;   // 0..15 : owns q rows 4*tq .. 4*tq+3
    const int tk  = tid & 15;   // 0..15 : S k-cols 4*tk.. ; PV d rows {4tk..+3, 64+4tk..+3}
    const int qbase = blockIdx.x * BQ;

    // ---- load Q tile: Qs[d][q] ----
    for (int u = tid; u < 128 * 16; u += THREADS) {
        const int d  = u >> 4;
        const int q4 = (u & 15) << 2;
        float4 v = *reinterpret_cast<const float4*>(&Q[(size_t)d * n + qbase + q4]);
        *reinterpret_cast<float4*>(&Qs[d * 64 + q4]) = v;
    }

    // softmax running state (replicated across the 16 threads sharing tq)
    float m[4], l[4];
#pragma unroll
    for (int i = 0; i < 4; i++) { m[i] = -CUDART_INF_F; l[i] = 0.f; }

    // O accumulators: oacc[i][p] = (O[d_i][q_{2p}], O[d_i][q_{2p+1}]) packed
    unsigned long long oacc[8][2];
#pragma unroll
    for (int i = 0; i < 8; i++) { oacc[i][0] = pack2(0.f, 0.f); oacc[i][1] = pack2(0.f, 0.f); }

    const int kkv = tid & 63;   // V-transpose loader: k index
    const int d0v = tid >> 6;   // V-transpose loader: d start (0..3)

    for (int kb = 0; kb < n; kb += BK) {
        __syncthreads();  // previous PV done reading Ks/Vts/Ps

        // ---- load K tile: Ks[d][k] ----
        for (int u = tid; u < 128 * 16; u += THREADS) {
            const int d  = u >> 4;
            const int k4 = (u & 15) << 2;
            float4 v = *reinterpret_cast<const float4*>(&K[(size_t)d * n + kb + k4]);
            *reinterpret_cast<float4*>(&Ks[d * 64 + k4]) = v;
        }
        // ---- load V tile transposed: Vts[k][d] ----
        for (int dd = d0v; dd < 128; dd += 4) {
            Vts[kkv * 132 + dd] = V[(size_t)dd * n + kb + kkv];
        }
        __syncthreads();

        // ---- S = Q^T K : s2[p][j] = (S[q_{2p}][k_j], S[q_{2p+1}][k_j]) ----
        unsigned long long s2[2][4];
#pragma unroll
        for (int j = 0; j < 4; j++) { s2[0][j] = pack2(0.f, 0.f); s2[1][j] = pack2(0.f, 0.f); }

#pragma unroll 8
        for (int d = 0; d < DHEAD; ++d) {
            float4 qv = *reinterpret_cast<const float4*>(&Qs[d * 64 + 4 * tq]);
            float4 kv = *reinterpret_cast<const float4*>(&Ks[d * 64 + 4 * tk]);
            unsigned long long qlo = pack2(qv.x, qv.y);
            unsigned long long qhi = pack2(qv.z, qv.w);
            const float kvv[4] = {kv.x, kv.y, kv.z, kv.w};
#pragma unroll
            for (int j = 0; j < 4; j++) {
                unsigned long long bb = pack2(kvv[j], kvv[j]);
                ffma2(s2[0][j], qlo, bb);
                ffma2(s2[1][j], qhi, bb);
            }
        }

        // ---- online softmax (rows spread over 16 threads = half-warp) ----
        float sv[4][4];
#pragma unroll
        for (int j = 0; j < 4; j++) {
            unpack2(s2[0][j], sv[0][j], sv[1][j]);
            unpack2(s2[1][j], sv[2][j], sv[3][j]);
        }

        float scale[4];
#pragma unroll
        for (int qi = 0; qi < 4; qi++) {
            float mt = fmaxf(fmaxf(sv[qi][0], sv[qi][1]), fmaxf(sv[qi][2], sv[qi][3]));
#pragma unroll
            for (int off = 1; off < 16; off <<= 1)
                mt = fmaxf(mt, __shfl_xor_sync(0xffffffffu, mt, off));
            const float mnew = fmaxf(m[qi], mt);
            scale[qi] = __expf(m[qi] - mnew);
            float lt = 0.f;
#pragma unroll
            for (int j = 0; j < 4; j++) {
                const float p = __expf(sv[qi][j] - mnew);
                sv[qi][j] = p;
                lt += p;
            }
#pragma unroll
            for (int off = 1; off < 16; off <<= 1)
                lt += __shfl_xor_sync(0xffffffffu, lt, off);
            l[qi] = l[qi] * scale[qi] + lt;
            m[qi] = mnew;
        }

        // rescale O accumulators by per-q scale
        {
            const unsigned long long sc0 = pack2(scale[0], scale[1]);
            const unsigned long long sc1 = pack2(scale[2], scale[3]);
#pragma unroll
            for (int i = 0; i < 8; i++) {
                oacc[i][0] = mul2(oacc[i][0], sc0);
                oacc[i][1] = mul2(oacc[i][1], sc1);
            }
        }

        // write P transposed: Ps[k][q] (one float4 across q per k)
#pragma unroll
        for (int j = 0; j < 4; j++) {
            float4 pv = make_float4(sv[0][j], sv[1][j], sv[2][j], sv[3][j]);
            *reinterpret_cast<float4*>(&Ps[(4 * tk + j) * 68 + 4 * tq]) = pv;
        }
        __syncthreads();

        // ---- O += V * P^T  : loop over k, rank-1 updates ----
#pragma unroll 2
        for (int k = 0; k < BK; k++) {
            float4 pv = *reinterpret_cast<const float4*>(&Ps[k * 68 + 4 * tq]);
            float4 va = *reinterpret_cast<const float4*>(&Vts[k * 132 + 4 * tk]);
            float4 vb = *reinterpret_cast<const float4*>(&Vts[k * 132 + 64 + 4 * tk]);
            const unsigned long long plo = pack2(pv.x, pv.y);
            const unsigned long long phi = pack2(pv.z, pv.w);
            const float vs[8] = {va.x, va.y, va.z, va.w, vb.x, vb.y, vb.z, vb.w};
#pragma unroll
            for (int i = 0; i < 8; i++) {
                unsigned long long vv = pack2(vs[i], vs[i]);
                ffma2(oacc[i][0], plo, vv);
                ffma2(oacc[i][1], phi, vv);
            }
        }
    }

    // ---- finalize: divide by l, store ----
    float linv[4];
#pragma unroll
    for (int qi = 0; qi < 4; qi++) linv[qi] = 1.0f / l[qi];
    const unsigned long long li0 = pack2(linv[0], linv[1]);
    const unsigned long long li1 = pack2(linv[2], linv[3]);

#pragma unroll
    for (int i = 0; i < 8; i++) {
        const int d = (i < 4) ? (4 * tk + i) : (64 + 4 * tk + (i - 4));
        unsigned long long a = mul2(oacc[i][0], li0);
        unsigned long long b = mul2(oacc[i][1], li1);
        float o0, o1, o2, o3;
        unpack2(a, o0, o1);
        unpack2(b, o2, o3);
        *reinterpret_cast<float4*>(&Out[(size_t)d * n + qbase + 4 * tq]) =
            make_float4(o0, o1, o2, o3);
    }
}

extern "C" void kernel_launch(void* const* d_in, const int* in_sizes, int n_in,
                              void* d_out, int out_size)
{
    const float* Q = (const float*)d_in[0];
    const float* K = (const float*)d_in[1];
    const float* V = (const float*)d_in[2];
    float* O = (float*)d_out;
    (void)n_in; (void)out_size;

    const int n = in_sizes[0] / DHEAD;   // 8192

    cudaFuncSetAttribute(attn_flash_f32x2_kernel,
                         cudaFuncAttributeMaxDynamicSharedMemorySize, SM_BYTES);

    attn_flash_f32x2_kernel<<<n / BQ, THREADS, SM_BYTES>>>(Q, K, V, O, n);
}